// round 2
// baseline (speedup 1.0000x reference)
#include <cuda_runtime.h>

#define DIMC 64
#define HID 384
#define QK 128
#define IMH 256
#define IMW 256
#define NB 4
#define THREADS 512
#define CHUNK 64
#define NCHUNK 6

// shared memory layout (floats):
// xs[64][128] x-tile (10x10 linearized to 100, padded row 128)
// ws[64][64]  staged w_hidden chunk, transposed [i][cl]
// hs[64][100] per-chunk hidden (pre-dw) scratch
// qT[64][132] q transposed: [pixel m][channel c]
// ksm[128][65] k: [channel][pixel]
// vsm[128][65] v: [channel][pixel]
// wdw[384][9] staged depthwise weights
// wpT[128][64] staged w_proj transposed [c][o]
// psum[8][64], psq[8][64], mean[64], rstd[64]
#define OFF_XS   0
#define OFF_WS   (OFF_XS + 64*128)
#define OFF_HS   (OFF_WS + 64*64)
#define OFF_QT   (OFF_HS + 64*100)
#define OFF_KSM  (OFF_QT + 64*132)
#define OFF_VSM  (OFF_KSM + 128*65)
#define OFF_WDW  (OFF_VSM + 128*65)
#define OFF_WPT  (OFF_WDW + 384*9)
#define OFF_PSUM (OFF_WPT + 128*64)
#define OFF_PSQ  (OFF_PSUM + 8*64)
#define OFF_MEAN (OFF_PSQ + 8*64)
#define OFF_RSTD (OFF_MEAN + 64)
#define SMEM_FLOATS (OFF_RSTD + 64)

extern __shared__ float smem[];

__global__ __launch_bounds__(THREADS, 1)
void fsas_kernel(const float* __restrict__ x,
                 const float* __restrict__ w_hidden,
                 const float* __restrict__ b_hidden,
                 const float* __restrict__ w_dw,
                 const float* __restrict__ b_dw,
                 const float* __restrict__ w_proj,
                 const float* __restrict__ b_proj,
                 const float* __restrict__ ln_w,
                 const float* __restrict__ ln_b,
                 float* __restrict__ out)
{
    float* xs   = smem + OFF_XS;
    float* ws   = smem + OFF_WS;
    float* hs   = smem + OFF_HS;
    float* qT   = smem + OFF_QT;
    float* ksm  = smem + OFF_KSM;
    float* vsm  = smem + OFF_VSM;
    float* wdw  = smem + OFF_WDW;
    float* wpT  = smem + OFF_WPT;
    float* psum = smem + OFF_PSUM;
    float* psq  = smem + OFF_PSQ;
    float* mean_s = smem + OFF_MEAN;
    float* rstd_s = smem + OFF_RSTD;

    const int t  = threadIdx.x;
    const int bx = blockIdx.x;          // patch col 0..31
    const int by = blockIdx.y;          // patch row 0..31
    const int bb = blockIdx.z;          // batch 0..3
    const int gx0 = bx * 8 - 1;
    const int gy0 = by * 8 - 1;

    // ---------- stage x tile (10x10 with zero halo), wdw, wpT ----------
    for (int idx = t; idx < 64 * 128; idx += THREADS) {
        int ic = idx >> 7, tp = idx & 127;
        float v = 0.f;
        if (tp < 100) {
            int ty = tp / 10, tx = tp - ty * 10;
            int gy = gy0 + ty, gx = gx0 + tx;
            if ((unsigned)gy < IMH && (unsigned)gx < IMW)
                v = x[((size_t)(bb * DIMC + ic) * IMH + gy) * IMW + gx];
        }
        xs[idx] = v;
    }
    for (int idx = t; idx < HID * 9; idx += THREADS)
        wdw[idx] = w_dw[idx];
    for (int idx = t; idx < DIMC * QK; idx += THREADS) {
        int o = idx >> 7, c = idx & 127;           // w_proj[o][c], QK=128
        wpT[c * 64 + o] = w_proj[idx];
    }
    __syncthreads();

    const int pxA = t & 127;       // tile pixel slot (valid < 100)
    const int cgA = t >> 7;        // 0..3 channel group for 1x1
    const int p8  = t & 63;        // patch pixel for dw / phase B
    const int i8  = p8 >> 3;
    const int j8  = p8 & 7;
    const int clg = t >> 6;        // 0..7 channel group for dw

    // 'SAME' padding on the dw conv zero-pads HIDDEN (post 1x1+bias) outside
    // the image; halo pixels that fall outside the image must contribute 0,
    // not b_hidden. Compute validity of this thread's tile pixel once.
    bool pvalid = false;
    if (pxA < 100) {
        int ty = pxA / 10, tx = pxA - ty * 10;
        int gy = gy0 + ty, gx = gx0 + tx;
        pvalid = ((unsigned)gy < IMH) && ((unsigned)gx < IMW);
    }

    // ================= Phase A: 1x1 conv + depthwise 3x3 =================
    for (int ch = 0; ch < NCHUNK; ++ch) {
        const int cbase = ch * CHUNK;
        // stage ws[i][cl] = w_hidden[cbase+cl][i]
        for (int idx = t; idx < 64 * 64; idx += THREADS) {
            int i = idx >> 6, cl = idx & 63;
            ws[idx] = w_hidden[(cbase + cl) * 64 + i];
        }
        __syncthreads();

        // 1x1: each thread -> 16 channels at one tile pixel
        const int c0 = cbase + cgA * 16;
        float h[16];
        #pragma unroll
        for (int j = 0; j < 16; ++j) h[j] = __ldg(&b_hidden[c0 + j]);

        #pragma unroll 8
        for (int i = 0; i < 64; ++i) {
            float xv = xs[i * 128 + pxA];
            const float4* wrow = (const float4*)(ws + i * 64 + cgA * 16);
            float4 w0 = wrow[0], w1 = wrow[1], w2 = wrow[2], w3 = wrow[3];
            h[0]  += xv * w0.x;  h[1]  += xv * w0.y;
            h[2]  += xv * w0.z;  h[3]  += xv * w0.w;
            h[4]  += xv * w1.x;  h[5]  += xv * w1.y;
            h[6]  += xv * w1.z;  h[7]  += xv * w1.w;
            h[8]  += xv * w2.x;  h[9]  += xv * w2.y;
            h[10] += xv * w2.z;  h[11] += xv * w2.w;
            h[12] += xv * w3.x;  h[13] += xv * w3.y;
            h[14] += xv * w3.z;  h[15] += xv * w3.w;
        }
        if (pxA < 100) {
            #pragma unroll
            for (int j = 0; j < 16; ++j)
                hs[(cgA * 16 + j) * 100 + pxA] = pvalid ? h[j] : 0.f;
        }
        __syncthreads();

        // depthwise 3x3 (cross-correlation, SAME zero-pad handled by halo)
        #pragma unroll
        for (int j = 0; j < 8; ++j) {
            int cl = clg * 8 + j;
            int c  = cbase + cl;
            float acc = __ldg(&b_dw[c]);
            const float* wd   = wdw + c * 9;
            const float* hrow = hs + cl * 100;
            #pragma unroll
            for (int dy = 0; dy < 3; ++dy)
                #pragma unroll
                for (int dx = 0; dx < 3; ++dx)
                    acc += hrow[(i8 + dy) * 10 + (j8 + dx)] * wd[dy * 3 + dx];
            if (ch < 2)      qT[p8 * 132 + c]          = acc;   // q: [pixel][ch]
            else if (ch < 4) ksm[(c - 128) * 65 + p8]  = acc;   // k: [ch][pixel]
            else             vsm[(c - 256) * 65 + p8]  = acc;   // v: [ch][pixel]
        }
        __syncthreads();
    }

    // ================= Phase B: circular conv (q (*) k per 8x8 patch) =================
    // thread: pixel p8, channels cgB*16 .. cgB*16+15
    const int cgB = clg;  // 0..7
    float acc[16];
    #pragma unroll
    for (int j = 0; j < 16; ++j) acc[j] = 0.f;

    #pragma unroll 2
    for (int a = 0; a < 8; ++a) {
        int ii = ((i8 - a) & 7) * 8;
        #pragma unroll
        for (int bq = 0; bq < 8; ++bq) {
            int m   = a * 8 + bq;
            int idx = ii + ((j8 - bq) & 7);
            const float4* qrow = (const float4*)(qT + m * 132 + cgB * 16);
            float4 q0 = qrow[0], q1 = qrow[1], q2 = qrow[2], q3 = qrow[3];
            const float* kb = ksm + (cgB * 16) * 65 + idx;
            acc[0]  += q0.x * kb[0  * 65];
            acc[1]  += q0.y * kb[1  * 65];
            acc[2]  += q0.z * kb[2  * 65];
            acc[3]  += q0.w * kb[3  * 65];
            acc[4]  += q1.x * kb[4  * 65];
            acc[5]  += q1.y * kb[5  * 65];
            acc[6]  += q1.z * kb[6  * 65];
            acc[7]  += q1.w * kb[7  * 65];
            acc[8]  += q2.x * kb[8  * 65];
            acc[9]  += q2.y * kb[9  * 65];
            acc[10] += q2.z * kb[10 * 65];
            acc[11] += q2.w * kb[11 * 65];
            acc[12] += q3.x * kb[12 * 65];
            acc[13] += q3.y * kb[13 * 65];
            acc[14] += q3.z * kb[14 * 65];
            acc[15] += q3.w * kb[15 * 65];
        }
    }

    // ---------- LayerNorm over 128 channels per pixel ----------
    float s1 = 0.f, s2 = 0.f;
    #pragma unroll
    for (int j = 0; j < 16; ++j) { s1 += acc[j]; s2 += acc[j] * acc[j]; }
    psum[cgB * 64 + p8] = s1;
    psq [cgB * 64 + p8] = s2;
    __syncthreads();
    if (t < 64) {
        float sm = 0.f, sq = 0.f;
        #pragma unroll
        for (int g = 0; g < 8; ++g) { sm += psum[g * 64 + t]; sq += psq[g * 64 + t]; }
        float mu  = sm * (1.f / 128.f);
        float var = sq * (1.f / 128.f) - mu * mu;
        mean_s[t] = mu;
        rstd_s[t] = rsqrtf(var + 1e-5f);
    }
    __syncthreads();

    // normalize, scale/shift, multiply by v; write into ksm (k no longer needed)
    {
        float mu = mean_s[p8], rs = rstd_s[p8];
        #pragma unroll
        for (int j = 0; j < 16; ++j) {
            int c = cgB * 16 + j;
            float o  = (acc[j] - mu) * rs * __ldg(&ln_w[c]) + __ldg(&ln_b[c]);
            float ov = vsm[c * 65 + p8] * o;
            ksm[c * 65 + p8] = ov;
        }
    }
    __syncthreads();

    // ---------- 1x1 projection 128 -> 64 ----------
    const int og = clg;  // 0..7, outputs og*8 .. og*8+7
    float r[8];
    #pragma unroll
    for (int j = 0; j < 8; ++j) r[j] = __ldg(&b_proj[og * 8 + j]);

    #pragma unroll 4
    for (int c = 0; c < 128; ++c) {
        float ov = ksm[c * 65 + p8];
        const float4* wrow = (const float4*)(wpT + c * 64 + og * 8);
        float4 w0 = wrow[0], w1 = wrow[1];
        r[0] += ov * w0.x;  r[1] += ov * w0.y;
        r[2] += ov * w0.z;  r[3] += ov * w0.w;
        r[4] += ov * w1.x;  r[5] += ov * w1.y;
        r[6] += ov * w1.z;  r[7] += ov * w1.w;
    }

    const int gy = by * 8 + i8;
    const int gx = bx * 8 + j8;
    #pragma unroll
    for (int j = 0; j < 8; ++j) {
        int o = og * 8 + j;
        out[((size_t)(bb * DIMC + o) * IMH + gy) * IMW + gx] = r[j];
    }
}

extern "C" void kernel_launch(void* const* d_in, const int* in_sizes, int n_in,
                              void* d_out, int out_size) {
    const float* x        = (const float*)d_in[0];
    const float* w_hidden = (const float*)d_in[1];
    const float* b_hidden = (const float*)d_in[2];
    const float* w_dw     = (const float*)d_in[3];
    const float* b_dw     = (const float*)d_in[4];
    const float* w_proj   = (const float*)d_in[5];
    const float* b_proj   = (const float*)d_in[6];
    const float* ln_w     = (const float*)d_in[7];
    const float* ln_b     = (const float*)d_in[8];
    float* out = (float*)d_out;

    const int smem_bytes = SMEM_FLOATS * sizeof(float);  // 226304 B
    cudaFuncSetAttribute(fsas_kernel, cudaFuncAttributeMaxDynamicSharedMemorySize, smem_bytes);

    dim3 grid(32, 32, 4);
    fsas_kernel<<<grid, THREADS, smem_bytes>>>(x, w_hidden, b_hidden, w_dw, b_dw,
                                               w_proj, b_proj, ln_w, ln_b, out);
}

// round 3
// speedup vs baseline: 1.5932x; 1.5932x over previous
#include <cuda_runtime.h>

#define THREADS 512
#define IMH 256
#define IMW 256

// shared memory offsets (floats)
#define OFF_XS    0          // [64][128] x tile; overlaid by wpT[128][68] after Phase A
#define OFF_WPT   0
#define OFF_WS    8192       // [64][132] staged w_hidden pass chunk, transposed
#define OFF_HS    16640      // [64][128] hidden scratch (one 64-ch half)
#define OFF_WDWP  24832      // [128][9] dw weights for pass
#define OFF_Q     25984      // [128][68]
#define OFF_K     34688      // [128][68]
#define OFF_V     43392      // [128][68]
#define OFF_PS    52096      // [8][66]
#define OFF_PQ    52624      // [8][66]
#define OFF_MEAN  53152      // [64]
#define OFF_RSTD  53216      // [64]
#define SMEM_FLOATS 53280    // 213120 bytes

extern __shared__ float smem[];

__global__ __launch_bounds__(THREADS, 1)
void fsas_kernel(const float* __restrict__ x,
                 const float* __restrict__ w_hidden,
                 const float* __restrict__ b_hidden,
                 const float* __restrict__ w_dw,
                 const float* __restrict__ b_dw,
                 const float* __restrict__ w_proj,
                 const float* __restrict__ b_proj,
                 const float* __restrict__ ln_w,
                 const float* __restrict__ ln_b,
                 float* __restrict__ out)
{
    float* xs    = smem + OFF_XS;
    float* wpT   = smem + OFF_WPT;
    float* ws    = smem + OFF_WS;
    float* hs    = smem + OFF_HS;
    float* wdwp  = smem + OFF_WDWP;
    float* qsm   = smem + OFF_Q;
    float* ksm   = smem + OFF_K;
    float* vsm   = smem + OFF_V;
    float* ps    = smem + OFF_PS;
    float* pq    = smem + OFF_PQ;
    float* mean_s = smem + OFF_MEAN;
    float* rstd_s = smem + OFF_RSTD;

    const int t  = threadIdx.x;
    const int bx = blockIdx.x;
    const int by = blockIdx.y;
    const int bb = blockIdx.z;
    const int gx0 = bx * 8 - 1;
    const int gy0 = by * 8 - 1;

    // ---------- stage x tile (10x10 halo, linearized tp=ty*10+tx in slots 0..99) ----------
    for (int idx = t; idx < 64 * 128; idx += THREADS) {
        int ic = idx >> 7, tp = idx & 127;
        float v = 0.f;
        if (tp < 100) {
            int ty = tp / 10, tx = tp - ty * 10;
            int gy = gy0 + ty, gx = gx0 + tx;
            if ((unsigned)gy < IMH && (unsigned)gx < IMW)
                v = x[((size_t)(bb * 64 + ic) * IMH + gy) * IMW + gx];
        }
        xs[idx] = v;
    }

    const int pg = t & 31;        // pixel group: pixels pg*4..pg*4+3
    const int cg = t >> 5;        // 0..15: channels cg*8..cg*8+7 (of 128 per pass)
    const int p8 = t & 63;        // patch pixel
    const int i8 = p8 >> 3;
    const int j8 = p8 & 7;
    const int cl8 = t >> 6;       // 0..7 (dw channel group)

    // validity of the 4 tile pixels (SAME-pad: hidden is zero outside image)
    bool vmask[4];
    #pragma unroll
    for (int l = 0; l < 4; ++l) {
        int tp = pg * 4 + l;
        bool ok = false;
        if (tp < 100) {
            int ty = tp / 10, tx = tp - ty * 10;
            int gy = gy0 + ty, gx = gx0 + tx;
            ok = ((unsigned)gy < IMH) && ((unsigned)gx < IMW);
        }
        vmask[l] = ok;
    }

    // ================= Phase A: 3 passes of 128 channels =================
    for (int pass = 0; pass < 3; ++pass) {
        const int pch = pass * 128;
        __syncthreads();
        // stage ws[i][c] = w_hidden[pch+c][i], row stride 132
        for (int idx = t; idx < 64 * 128; idx += THREADS) {
            int i = idx & 63, c = idx >> 6;
            ws[i * 132 + c] = w_hidden[(pch + c) * 64 + i];
        }
        // stage dw weights for this pass
        for (int idx = t; idx < 128 * 9; idx += THREADS)
            wdwp[idx] = w_dw[pch * 9 + idx];
        __syncthreads();

        // 1x1 conv: acc[ch j][px l]
        float acc[8][4];
        #pragma unroll
        for (int j = 0; j < 8; ++j) {
            float b = __ldg(&b_hidden[pch + cg * 8 + j]);
            acc[j][0] = b; acc[j][1] = b; acc[j][2] = b; acc[j][3] = b;
        }
        const float* xsp = xs + pg * 4;
        const float* wsp = ws + cg * 8;
        #pragma unroll 4
        for (int i = 0; i < 64; ++i) {
            float4 xv = *(const float4*)(xsp + i * 128);
            float4 w0 = *(const float4*)(wsp + i * 132);
            float4 w1 = *(const float4*)(wsp + i * 132 + 4);
            float wv[8] = {w0.x, w0.y, w0.z, w0.w, w1.x, w1.y, w1.z, w1.w};
            #pragma unroll
            for (int j = 0; j < 8; ++j) {
                acc[j][0] += wv[j] * xv.x;
                acc[j][1] += wv[j] * xv.y;
                acc[j][2] += wv[j] * xv.z;
                acc[j][3] += wv[j] * xv.w;
            }
        }

        float* dst = (pass == 0) ? qsm : (pass == 1) ? ksm : vsm;

        // two 64-channel halves through hs
        #pragma unroll
        for (int h = 0; h < 2; ++h) {
            if ((cg >> 3) == h) {
                #pragma unroll
                for (int j = 0; j < 8; ++j) {
                    int lc = (cg & 7) * 8 + j;
                    float4 hv = make_float4(vmask[0] ? acc[j][0] : 0.f,
                                            vmask[1] ? acc[j][1] : 0.f,
                                            vmask[2] ? acc[j][2] : 0.f,
                                            vmask[3] ? acc[j][3] : 0.f);
                    *(float4*)(hs + lc * 128 + pg * 4) = hv;
                }
            }
            __syncthreads();

            // depthwise 3x3 on this half -> q/k/v [c][68]
            #pragma unroll
            for (int jj = 0; jj < 8; ++jj) {
                int lc = cl8 * 8 + jj;
                int gc = pch + h * 64 + lc;
                float a = __ldg(&b_dw[gc]);
                const float* hr = hs + lc * 128 + i8 * 10 + j8;
                const float* wd = wdwp + (h * 64 + lc) * 9;
                #pragma unroll
                for (int dy = 0; dy < 3; ++dy)
                    #pragma unroll
                    for (int dx = 0; dx < 3; ++dx)
                        a += hr[dy * 10 + dx] * wd[dy * 3 + dx];
                dst[(h * 64 + lc) * 68 + p8] = a;
            }
            __syncthreads();
        }
    }

    // stage wpT[c][68] = w_proj[o][c]  (overlays dead xs/ws)
    for (int idx = t; idx < 64 * 128; idx += THREADS) {
        int c = idx & 127, o = idx >> 7;
        wpT[c * 68 + o] = w_proj[o * 128 + c];
    }
    // note: plenty of syncs before proj reads wpT

    // ================= Phase B: circular conv per 8x8 patch =================
    // thread: one channel c, two pixel rows i0, i0+1
    const int lane = t & 31;
    const int warp = t >> 5;
    const int csub = lane >> 2;       // 0..7
    const int pxg  = lane & 3;        // 0..3
    const int c    = warp * 8 + csub; // 0..127
    const int i0   = pxg * 2;

    float bacc[2][8];
    #pragma unroll
    for (int di = 0; di < 2; ++di)
        #pragma unroll
        for (int j = 0; j < 8; ++j) bacc[di][j] = 0.f;

    {
        const float* qrow = qsm + c * 68;
        const float* krow = ksm + c * 68;
        #pragma unroll
        for (int a = 0; a < 8; ++a) {
            float4 qa = *(const float4*)(qrow + a * 8);
            float4 qb = *(const float4*)(qrow + a * 8 + 4);
            float qq[8] = {qa.x, qa.y, qa.z, qa.w, qb.x, qb.y, qb.z, qb.w};
            int r0 = (i0 - a) & 7;
            int r1 = (r0 + 1) & 7;
            float4 ka0 = *(const float4*)(krow + r0 * 8);
            float4 ka1 = *(const float4*)(krow + r0 * 8 + 4);
            float4 kb0 = *(const float4*)(krow + r1 * 8);
            float4 kb1 = *(const float4*)(krow + r1 * 8 + 4);
            float k0[8] = {ka0.x, ka0.y, ka0.z, ka0.w, ka1.x, ka1.y, ka1.z, ka1.w};
            float k1[8] = {kb0.x, kb0.y, kb0.z, kb0.w, kb1.x, kb1.y, kb1.z, kb1.w};
            #pragma unroll
            for (int b = 0; b < 8; ++b) {
                #pragma unroll
                for (int j = 0; j < 8; ++j) {
                    int kc = (j - b) & 7;
                    bacc[0][j] += qq[b] * k0[kc];
                    bacc[1][j] += qq[b] * k1[kc];
                }
            }
        }
    }
    __syncthreads();

    // write Phase-B output to osm (= qsm, q is dead) for the LN reduction
    #pragma unroll
    for (int di = 0; di < 2; ++di) {
        int row = i0 + di;
        *(float4*)(qsm + c * 68 + row * 8)     = make_float4(bacc[di][0], bacc[di][1], bacc[di][2], bacc[di][3]);
        *(float4*)(qsm + c * 68 + row * 8 + 4) = make_float4(bacc[di][4], bacc[di][5], bacc[di][6], bacc[di][7]);
    }
    __syncthreads();

    // ---------- LayerNorm stats over 128 channels per pixel ----------
    {
        int px = t & 63, g = t >> 6;    // g: 16-channel group
        float s = 0.f, ss = 0.f;
        #pragma unroll 4
        for (int cc = g * 16; cc < g * 16 + 16; ++cc) {
            float v = qsm[cc * 68 + px];
            s += v; ss += v * v;
        }
        ps[g * 66 + px] = s;
        pq[g * 66 + px] = ss;
    }
    __syncthreads();
    if (t < 64) {
        float sm = 0.f, sq = 0.f;
        #pragma unroll
        for (int g = 0; g < 8; ++g) { sm += ps[g * 66 + t]; sq += pq[g * 66 + t]; }
        float mu  = sm * (1.f / 128.f);
        float var = sq * (1.f / 128.f) - mu * mu;
        mean_s[t] = mu;
        rstd_s[t] = rsqrtf(var + 1e-5f);
    }
    __syncthreads();

    // ---------- normalize, scale/shift, multiply by v -> ovsm (= ksm, k dead) ----------
    {
        float lw = __ldg(&ln_w[c]);
        float lb = __ldg(&ln_b[c]);
        #pragma unroll
        for (int di = 0; di < 2; ++di) {
            int row = i0 + di;
            float4 v0 = *(const float4*)(vsm + c * 68 + row * 8);
            float4 v1 = *(const float4*)(vsm + c * 68 + row * 8 + 4);
            float vv[8] = {v0.x, v0.y, v0.z, v0.w, v1.x, v1.y, v1.z, v1.w};
            float ov[8];
            #pragma unroll
            for (int j = 0; j < 8; ++j) {
                int px = row * 8 + j;
                float o = (bacc[di][j] - mean_s[px]) * rstd_s[px] * lw + lb;
                ov[j] = vv[j] * o;
            }
            *(float4*)(ksm + c * 68 + row * 8)     = make_float4(ov[0], ov[1], ov[2], ov[3]);
            *(float4*)(ksm + c * 68 + row * 8 + 4) = make_float4(ov[4], ov[5], ov[6], ov[7]);
        }
    }
    __syncthreads();

    // ---------- 1x1 projection 128 -> 64 ----------
    {
        const int og = t >> 6;   // 0..7: outputs og*8..og*8+7
        float r[8];
        #pragma unroll
        for (int j = 0; j < 8; ++j) r[j] = __ldg(&b_proj[og * 8 + j]);

        #pragma unroll 8
        for (int cc = 0; cc < 128; ++cc) {
            float ov = ksm[cc * 68 + p8];
            float4 w0 = *(const float4*)(wpT + cc * 68 + og * 8);
            float4 w1 = *(const float4*)(wpT + cc * 68 + og * 8 + 4);
            r[0] += ov * w0.x;  r[1] += ov * w0.y;
            r[2] += ov * w0.z;  r[3] += ov * w0.w;
            r[4] += ov * w1.x;  r[5] += ov * w1.y;
            r[6] += ov * w1.z;  r[7] += ov * w1.w;
        }

        const int gy = by * 8 + i8;
        const int gx = bx * 8 + j8;
        #pragma unroll
        for (int j = 0; j < 8; ++j) {
            int o = og * 8 + j;
            out[((size_t)(bb * 64 + o) * IMH + gy) * IMW + gx] = r[j];
        }
    }
}

extern "C" void kernel_launch(void* const* d_in, const int* in_sizes, int n_in,
                              void* d_out, int out_size) {
    const float* x        = (const float*)d_in[0];
    const float* w_hidden = (const float*)d_in[1];
    const float* b_hidden = (const float*)d_in[2];
    const float* w_dw     = (const float*)d_in[3];
    const float* b_dw     = (const float*)d_in[4];
    const float* w_proj   = (const float*)d_in[5];
    const float* b_proj   = (const float*)d_in[6];
    const float* ln_w     = (const float*)d_in[7];
    const float* ln_b     = (const float*)d_in[8];
    float* out = (float*)d_out;

    const int smem_bytes = SMEM_FLOATS * sizeof(float);  // 213120 B
    cudaFuncSetAttribute(fsas_kernel, cudaFuncAttributeMaxDynamicSharedMemorySize, smem_bytes);

    dim3 grid(32, 32, 4);
    fsas_kernel<<<grid, THREADS, smem_bytes>>>(x, w_hidden, b_hidden, w_dw, b_dw,
                                               w_proj, b_proj, ln_w, ln_b, out);
}